// round 1
// baseline (speedup 1.0000x reference)
#include <cuda_runtime.h>

#define NN 100000
#define DD 128

// Scratch (allocation-free rule: __device__ globals)
__device__ float g_agg[(size_t)NN * DD];
__device__ float g_h1[(size_t)NN * DD];
__device__ float g_invdeg[NN];
__device__ float g_wcat[2][256 * DD];   // [layer][k(0..255)][o(0..127)]  k<128: W_neigh[o][k], else W_self[o][k-128]
__device__ float g_bias[2][DD];

// ---------------------------------------------------------------------------
__global__ void zero_kernel(float* __restrict__ p, int n4) {
    int i = blockIdx.x * blockDim.x + threadIdx.x;
    if (i < n4) ((float4*)p)[i] = make_float4(0.f, 0.f, 0.f, 0.f);
}

__global__ void deg_kernel(const int* __restrict__ dst, int E) {
    int e = blockIdx.x * blockDim.x + threadIdx.x;
    if (e < E) atomicAdd(&g_invdeg[dst[e]], 1.0f);
}

__global__ void invdeg_kernel(int n) {
    int i = blockIdx.x * blockDim.x + threadIdx.x;
    if (i < n) g_invdeg[i] = 1.0f / fmaxf(g_invdeg[i], 1.0f);
}

__global__ void prep_w_kernel(const float* __restrict__ Wn1, const float* __restrict__ bn1,
                              const float* __restrict__ Ws1, const float* __restrict__ bs1,
                              const float* __restrict__ Wn2, const float* __restrict__ bn2,
                              const float* __restrict__ Ws2, const float* __restrict__ bs2) {
    int idx = blockIdx.x * blockDim.x + threadIdx.x;
    if (idx < 256 * DD) {
        int k = idx / DD, o = idx % DD;
        g_wcat[0][idx] = (k < DD) ? Wn1[o * DD + k] : Ws1[o * DD + (k - DD)];
        g_wcat[1][idx] = (k < DD) ? Wn2[o * DD + k] : Ws2[o * DD + (k - DD)];
    }
    if (idx < DD) {
        g_bias[0][idx] = bn1[idx] + bs1[idx];
        g_bias[1][idx] = bn2[idx] + bs2[idx];
    }
}

// One warp per edge: 32 lanes x float4 = 128 features. Coalesced gather,
// atomic scatter-add (RED) into agg[dst].
__global__ void scatter_kernel(const float* __restrict__ feat,
                               const int* __restrict__ src,
                               const int* __restrict__ dst, int E) {
    unsigned id = blockIdx.x * blockDim.x + threadIdx.x;
    unsigned e = id >> 5;
    if (e >= (unsigned)E) return;
    int c = (id & 31u) << 2;
    int s = src[e], d = dst[e];
    float4 v = *(const float4*)(feat + (size_t)s * DD + c);
    float* o = g_agg + (size_t)d * DD + c;
    atomicAdd(o + 0, v.x);
    atomicAdd(o + 1, v.y);
    atomicAdd(o + 2, v.z);
    atomicAdd(o + 3, v.w);
}

// ---------------------------------------------------------------------------
// Fused SGEMM: out[r][o] = relu?( sum_k<128 agg[r][k]*invdeg[r]*Wcat[k][o]
//                                + sum_k A2[r][k]*Wcat[128+k][o] + bias[o] )
// Tile: BM=128, BN=128, BK=8; 256 threads, 8x8 register tile each.
template <bool RELU>
__global__ __launch_bounds__(256) void gemm_kernel(const float* __restrict__ A2,
                                                   const float* __restrict__ Wcat,
                                                   const float* __restrict__ bias,
                                                   float* __restrict__ out, int n) {
    __shared__ float As[8][128];
    __shared__ float Bs[8][128];

    const int tid = threadIdx.x;
    const int block_row = blockIdx.x * 128;

    // A-load mapping: each thread loads one float4 of A per k-step
    const int a_row = tid >> 1;            // 0..127
    const int a_k   = (tid & 1) << 2;      // 0 or 4
    const int g_row = block_row + a_row;
    const bool row_ok = g_row < n;
    const float ainv = row_ok ? g_invdeg[g_row] : 0.f;
    const float* a1p = g_agg + (size_t)g_row * DD;
    const float* a2p = A2 + (size_t)g_row * DD;

    // B-load mapping
    const int b_k   = tid >> 5;            // 0..7
    const int b_col = (tid & 31) << 2;     // 0..124

    // compute mapping: 16x16 thread grid, each 8x8
    const int tr = (tid >> 4) << 3;
    const int tc = (tid & 15) << 3;

    float acc[8][8];
#pragma unroll
    for (int i = 0; i < 8; i++)
#pragma unroll
        for (int j = 0; j < 8; j++) acc[i][j] = 0.f;

    for (int k0 = 0; k0 < 256; k0 += 8) {
        float4 av = make_float4(0.f, 0.f, 0.f, 0.f);
        const int kk = k0 + a_k;
        if (row_ok) {
            if (kk < 128) {
                av = *(const float4*)(a1p + kk);
                av.x *= ainv; av.y *= ainv; av.z *= ainv; av.w *= ainv;
            } else {
                av = *(const float4*)(a2p + (kk - 128));
            }
        }
        const float4 bv = *(const float4*)(Wcat + (size_t)(k0 + b_k) * 128 + b_col);

        if (k0) __syncthreads();
        As[a_k + 0][a_row] = av.x;
        As[a_k + 1][a_row] = av.y;
        As[a_k + 2][a_row] = av.z;
        As[a_k + 3][a_row] = av.w;
        *(float4*)&Bs[b_k][b_col] = bv;
        __syncthreads();

#pragma unroll
        for (int p = 0; p < 8; p++) {
            float ar[8], br[8];
#pragma unroll
            for (int i = 0; i < 8; i++) ar[i] = As[p][tr + i];
#pragma unroll
            for (int j = 0; j < 8; j++) br[j] = Bs[p][tc + j];
#pragma unroll
            for (int i = 0; i < 8; i++)
#pragma unroll
                for (int j = 0; j < 8; j++) acc[i][j] = fmaf(ar[i], br[j], acc[i][j]);
        }
    }

    // epilogue: bias (+relu), vectorized stores
    float bb[8];
#pragma unroll
    for (int j = 0; j < 8; j++) bb[j] = bias[tc + j];

#pragma unroll
    for (int i = 0; i < 8; i++) {
        int r = block_row + tr + i;
        if (r < n) {
            float v[8];
#pragma unroll
            for (int j = 0; j < 8; j++) {
                v[j] = acc[i][j] + bb[j];
                if (RELU) v[j] = fmaxf(v[j], 0.f);
            }
            float* op = out + (size_t)r * DD + tc;
            *(float4*)(op)     = make_float4(v[0], v[1], v[2], v[3]);
            *(float4*)(op + 4) = make_float4(v[4], v[5], v[6], v[7]);
        }
    }
}

// ---------------------------------------------------------------------------
extern "C" void kernel_launch(void* const* d_in, const int* in_sizes, int n_in,
                              void* d_out, int out_size) {
    const float* x   = (const float*)d_in[0];
    const int* ei    = (const int*)d_in[1];
    const float* Wn1 = (const float*)d_in[2];
    const float* bn1 = (const float*)d_in[3];
    const float* Ws1 = (const float*)d_in[4];
    const float* bs1 = (const float*)d_in[5];
    const float* Wn2 = (const float*)d_in[6];
    const float* bn2 = (const float*)d_in[7];
    const float* Ws2 = (const float*)d_in[8];
    const float* bs2 = (const float*)d_in[9];
    float* out = (float*)d_out;

    const int n = in_sizes[0] / DD;
    const int E = in_sizes[1] / 2;
    const int* src = ei;
    const int* dst = ei + E;

    float* d_agg;
    float* d_invdeg;
    float* d_h1;
    cudaGetSymbolAddress((void**)&d_agg, g_agg);
    cudaGetSymbolAddress((void**)&d_invdeg, g_invdeg);
    cudaGetSymbolAddress((void**)&d_h1, g_h1);

    float* d_wcat0;
    cudaGetSymbolAddress((void**)&d_wcat0, g_wcat);
    float* d_bias0;
    cudaGetSymbolAddress((void**)&d_bias0, g_bias);

    const int threads = 256;
    const int agg4 = (n * DD) / 4;
    const int inv4 = n / 4;

    // degree + normalization
    zero_kernel<<<(inv4 + threads - 1) / threads, threads>>>(d_invdeg, inv4);
    zero_kernel<<<(agg4 + threads - 1) / threads, threads>>>(d_agg, agg4);
    prep_w_kernel<<<(256 * DD + threads - 1) / threads, threads>>>(Wn1, bn1, Ws1, bs1,
                                                                   Wn2, bn2, Ws2, bs2);
    deg_kernel<<<(E + threads - 1) / threads, threads>>>(dst, E);
    invdeg_kernel<<<(n + threads - 1) / threads, threads>>>(n);

    // layer 1: aggregate x, fused GEMM + relu -> h1
    {
        unsigned total = (unsigned)E * 32u;
        scatter_kernel<<<(total + threads - 1) / threads, threads>>>(x, src, dst, E);
    }
    gemm_kernel<true><<<(n + 127) / 128, 256>>>(x, d_wcat0, d_bias0, d_h1, n);

    // layer 2: aggregate h1, fused GEMM -> out
    zero_kernel<<<(agg4 + threads - 1) / threads, threads>>>(d_agg, agg4);
    {
        unsigned total = (unsigned)E * 32u;
        scatter_kernel<<<(total + threads - 1) / threads, threads>>>(d_h1, src, dst, E);
    }
    gemm_kernel<false><<<(n + 127) / 128, 256>>>(d_h1, d_wcat0 + 256 * DD, d_bias0 + DD,
                                                 out, n);
}

// round 2
// speedup vs baseline: 1.9706x; 1.9706x over previous
#include <cuda_runtime.h>

#define NN 100000
#define DD 128
#define EE_MAX 1700000

// Scratch (allocation-free rule: __device__ globals)
__device__ float g_agg[(size_t)NN * DD];
__device__ float g_h1[(size_t)NN * DD];
__device__ int   g_deg[NN];
__device__ int   g_cursor[NN];
__device__ int   g_rowptr[NN + 1];
__device__ int   g_col[EE_MAX];
__device__ float g_wcat[2][256 * DD];   // [layer][k(0..255)][o(0..127)]
__device__ float g_bias[2][DD];

// ---------------------------------------------------------------------------
__global__ void zero_int2_kernel(int* __restrict__ a, int* __restrict__ b, int n) {
    int i = blockIdx.x * blockDim.x + threadIdx.x;
    if (i < n) { a[i] = 0; b[i] = 0; }
}

__global__ void deg_kernel(const int* __restrict__ dst, int E) {
    int e = blockIdx.x * blockDim.x + threadIdx.x;
    if (e < E) atomicAdd(&g_deg[dst[e]], 1);
}

// Single-block exclusive scan of g_deg -> g_rowptr (n up to ~100k)
__global__ __launch_bounds__(1024) void scan_kernel(int n) {
    __shared__ int sums[1024];
    const int t = threadIdx.x;
    const int chunk = (n + 1023) / 1024;
    const int beg = t * chunk;
    const int end = min(beg + chunk, n);
    int s = 0;
    for (int i = beg; i < end; i++) s += g_deg[i];
    sums[t] = s;
    __syncthreads();
    // Hillis-Steele inclusive scan
    for (int off = 1; off < 1024; off <<= 1) {
        int v = (t >= off) ? sums[t - off] : 0;
        __syncthreads();
        sums[t] += v;
        __syncthreads();
    }
    int run = t ? sums[t - 1] : 0;
    for (int i = beg; i < end; i++) {
        g_rowptr[i] = run;
        run += g_deg[i];
    }
    if (t == 1023) g_rowptr[n] = run;
}

__global__ void fill_kernel(const int* __restrict__ src, const int* __restrict__ dst, int E) {
    int e = blockIdx.x * blockDim.x + threadIdx.x;
    if (e < E) {
        int d = dst[e];
        int p = atomicAdd(&g_cursor[d], 1);
        g_col[g_rowptr[d] + p] = src[e];
    }
}

__global__ void prep_w_kernel(const float* __restrict__ Wn1, const float* __restrict__ bn1,
                              const float* __restrict__ Ws1, const float* __restrict__ bs1,
                              const float* __restrict__ Wn2, const float* __restrict__ bn2,
                              const float* __restrict__ Ws2, const float* __restrict__ bs2) {
    int idx = blockIdx.x * blockDim.x + threadIdx.x;
    if (idx < 256 * DD) {
        int k = idx / DD, o = idx % DD;
        g_wcat[0][idx] = (k < DD) ? Wn1[o * DD + k] : Ws1[o * DD + (k - DD)];
        g_wcat[1][idx] = (k < DD) ? Wn2[o * DD + k] : Ws2[o * DD + (k - DD)];
    }
    if (idx < DD) {
        g_bias[0][idx] = bn1[idx] + bs1[idx];
        g_bias[1][idx] = bn2[idx] + bs2[idx];
    }
}

// ---------------------------------------------------------------------------
// Gather-side mean aggregation: one warp per node. 32 lanes x float4 = 128
// features accumulated in registers; neighbor ids loaded coalesced (32/iter)
// and register-broadcast via shfl. Output pre-normalized by 1/max(deg,1).
__global__ __launch_bounds__(256) void agg_kernel(const float* __restrict__ feat,
                                                  float* __restrict__ out, int n) {
    const int warp = (blockIdx.x * blockDim.x + threadIdx.x) >> 5;
    if (warp >= n) return;
    const int lane = threadIdx.x & 31;
    const int c = lane << 2;
    const int beg = g_rowptr[warp];
    const int end = g_rowptr[warp + 1];

    float ax = 0.f, ay = 0.f, az = 0.f, aw = 0.f;
    for (int base = beg; base < end; base += 32) {
        const int idx = base + lane;
        const int sv = (idx < end) ? g_col[idx] : 0;
        const int cnt = min(end - base, 32);
#pragma unroll 4
        for (int j = 0; j < cnt; j++) {
            const int s = __shfl_sync(0xffffffffu, sv, j);
            const float4 v = *(const float4*)(feat + (size_t)s * DD + c);
            ax += v.x; ay += v.y; az += v.z; aw += v.w;
        }
    }
    const float inv = 1.0f / fmaxf((float)(end - beg), 1.0f);
    float4 r;
    r.x = ax * inv; r.y = ay * inv; r.z = az * inv; r.w = aw * inv;
    *(float4*)(out + (size_t)warp * DD + c) = r;
}

// ---------------------------------------------------------------------------
// Fused SGEMM: out[r][o] = relu?( sum_k<128 agg[r][k]*Wcat[k][o]
//                                + sum_k A2[r][k]*Wcat[128+k][o] + bias[o] )
// Tile: BM=128, BN=128, BK=8; 256 threads, 8x8 register tile each.
template <bool RELU>
__global__ __launch_bounds__(256) void gemm_kernel(const float* __restrict__ A2,
                                                   const float* __restrict__ Wcat,
                                                   const float* __restrict__ bias,
                                                   float* __restrict__ out, int n) {
    __shared__ float As[8][128];
    __shared__ float Bs[8][128];

    const int tid = threadIdx.x;
    const int block_row = blockIdx.x * 128;

    const int a_row = tid >> 1;            // 0..127
    const int a_k   = (tid & 1) << 2;      // 0 or 4
    const int g_row = block_row + a_row;
    const bool row_ok = g_row < n;
    const float* a1p = g_agg + (size_t)g_row * DD;
    const float* a2p = A2 + (size_t)g_row * DD;

    const int b_k   = tid >> 5;            // 0..7
    const int b_col = (tid & 31) << 2;     // 0..124

    const int tr = (tid >> 4) << 3;
    const int tc = (tid & 15) << 3;

    float acc[8][8];
#pragma unroll
    for (int i = 0; i < 8; i++)
#pragma unroll
        for (int j = 0; j < 8; j++) acc[i][j] = 0.f;

    for (int k0 = 0; k0 < 256; k0 += 8) {
        float4 av = make_float4(0.f, 0.f, 0.f, 0.f);
        const int kk = k0 + a_k;
        if (row_ok) {
            av = (kk < 128) ? *(const float4*)(a1p + kk)
                            : *(const float4*)(a2p + (kk - 128));
        }
        const float4 bv = *(const float4*)(Wcat + (size_t)(k0 + b_k) * 128 + b_col);

        if (k0) __syncthreads();
        As[a_k + 0][a_row] = av.x;
        As[a_k + 1][a_row] = av.y;
        As[a_k + 2][a_row] = av.z;
        As[a_k + 3][a_row] = av.w;
        *(float4*)&Bs[b_k][b_col] = bv;
        __syncthreads();

#pragma unroll
        for (int p = 0; p < 8; p++) {
            float ar[8], br[8];
#pragma unroll
            for (int i = 0; i < 8; i++) ar[i] = As[p][tr + i];
#pragma unroll
            for (int j = 0; j < 8; j++) br[j] = Bs[p][tc + j];
#pragma unroll
            for (int i = 0; i < 8; i++)
#pragma unroll
                for (int j = 0; j < 8; j++) acc[i][j] = fmaf(ar[i], br[j], acc[i][j]);
        }
    }

    float bb[8];
#pragma unroll
    for (int j = 0; j < 8; j++) bb[j] = bias[tc + j];

#pragma unroll
    for (int i = 0; i < 8; i++) {
        int r = block_row + tr + i;
        if (r < n) {
            float v[8];
#pragma unroll
            for (int j = 0; j < 8; j++) {
                v[j] = acc[i][j] + bb[j];
                if (RELU) v[j] = fmaxf(v[j], 0.f);
            }
            float* op = out + (size_t)r * DD + tc;
            *(float4*)(op)     = make_float4(v[0], v[1], v[2], v[3]);
            *(float4*)(op + 4) = make_float4(v[4], v[5], v[6], v[7]);
        }
    }
}

// ---------------------------------------------------------------------------
extern "C" void kernel_launch(void* const* d_in, const int* in_sizes, int n_in,
                              void* d_out, int out_size) {
    const float* x   = (const float*)d_in[0];
    const int* ei    = (const int*)d_in[1];
    const float* Wn1 = (const float*)d_in[2];
    const float* bn1 = (const float*)d_in[3];
    const float* Ws1 = (const float*)d_in[4];
    const float* bs1 = (const float*)d_in[5];
    const float* Wn2 = (const float*)d_in[6];
    const float* bn2 = (const float*)d_in[7];
    const float* Ws2 = (const float*)d_in[8];
    const float* bs2 = (const float*)d_in[9];
    float* out = (float*)d_out;

    const int n = in_sizes[0] / DD;
    const int E = in_sizes[1] / 2;
    const int* src = ei;
    const int* dst = ei + E;

    float* d_h1;    cudaGetSymbolAddress((void**)&d_h1, g_h1);
    float* d_agg;   cudaGetSymbolAddress((void**)&d_agg, g_agg);
    int* d_deg;     cudaGetSymbolAddress((void**)&d_deg, g_deg);
    int* d_cursor;  cudaGetSymbolAddress((void**)&d_cursor, g_cursor);
    float* d_wcat0; cudaGetSymbolAddress((void**)&d_wcat0, g_wcat);
    float* d_bias0; cudaGetSymbolAddress((void**)&d_bias0, g_bias);

    const int threads = 256;

    // --- CSR build (per launch; graph-capturable, no allocs) ---
    zero_int2_kernel<<<(n + threads - 1) / threads, threads>>>(d_deg, d_cursor, n);
    prep_w_kernel<<<(256 * DD + threads - 1) / threads, threads>>>(Wn1, bn1, Ws1, bs1,
                                                                   Wn2, bn2, Ws2, bs2);
    deg_kernel<<<(E + threads - 1) / threads, threads>>>(dst, E);
    scan_kernel<<<1, 1024>>>(n);
    fill_kernel<<<(E + threads - 1) / threads, threads>>>(src, dst, E);

    const unsigned agg_threads_total = (unsigned)n * 32u;
    const unsigned agg_blocks = (agg_threads_total + threads - 1) / threads;

    // layer 1: mean-aggregate x -> agg, fused GEMM + relu -> h1
    agg_kernel<<<agg_blocks, threads>>>(x, d_agg, n);
    gemm_kernel<true><<<(n + 127) / 128, 256>>>(x, d_wcat0, d_bias0, d_h1, n);

    // layer 2: mean-aggregate h1 -> agg, fused GEMM -> out
    agg_kernel<<<agg_blocks, threads>>>(d_h1, d_agg, n);
    gemm_kernel<false><<<(n + 127) / 128, 256>>>(d_h1, d_wcat0 + 256 * DD, d_bias0 + DD,
                                                 out, n);
}

// round 3
// speedup vs baseline: 2.6146x; 1.3268x over previous
#include <cuda_runtime.h>

#define NN 100000
#define DD 128
#define EE_MAX 1700000

// Scratch (allocation-free rule: __device__ globals)
__device__ float g_agg[(size_t)NN * DD];
__device__ float g_h1[(size_t)NN * DD];
__device__ int   g_deg[NN];
__device__ int   g_cursor[NN];
__device__ int   g_rowptr[NN + 1];
__device__ int   g_col[EE_MAX];
__device__ int   g_partial[128];
__device__ int   g_total;
__device__ float g_wcat[2][256 * DD];   // [layer][k(0..255)][o(0..127)]
__device__ float g_bias[2][DD];

// ---------------------------------------------------------------------------
__global__ void zero_int2_kernel(int* __restrict__ a, int* __restrict__ b, int n) {
    int i = blockIdx.x * blockDim.x + threadIdx.x;
    if (i < n) { a[i] = 0; b[i] = 0; }
}

__global__ void deg_kernel(const int* __restrict__ dst, int E) {
    int e = blockIdx.x * blockDim.x + threadIdx.x;
    if (e < E) atomicAdd(&g_deg[dst[e]], 1);
}

// --- three-phase exclusive scan of g_deg -> g_rowptr -----------------------
__global__ __launch_bounds__(1024) void scanA_kernel(int n) {
    const int i = blockIdx.x * 1024 + threadIdx.x;
    const int lane = threadIdx.x & 31;
    const int w = threadIdx.x >> 5;
    const int v = (i < n) ? g_deg[i] : 0;
    int s = v;
#pragma unroll
    for (int o = 1; o < 32; o <<= 1) {
        int t = __shfl_up_sync(0xffffffffu, s, o);
        if (lane >= o) s += t;
    }
    __shared__ int wsum[32];
    if (lane == 31) wsum[w] = s;
    __syncthreads();
    if (w == 0) {
        int ws = wsum[lane];
#pragma unroll
        for (int o = 1; o < 32; o <<= 1) {
            int t = __shfl_up_sync(0xffffffffu, ws, o);
            if (lane >= o) ws += t;
        }
        wsum[lane] = ws;
    }
    __syncthreads();
    const int excl = s - v + (w ? wsum[w - 1] : 0);
    if (i < n) g_rowptr[i] = excl;
    if (threadIdx.x == 1023) g_partial[blockIdx.x] = excl + v;  // block total
}

__global__ __launch_bounds__(128) void scanB_kernel(int nb) {
    __shared__ int s[128];
    const int t = threadIdx.x;
    s[t] = (t < nb) ? g_partial[t] : 0;
    __syncthreads();
    for (int o = 1; o < 128; o <<= 1) {
        int x = (t >= o) ? s[t - o] : 0;
        __syncthreads();
        s[t] += x;
        __syncthreads();
    }
    g_partial[t] = t ? s[t - 1] : 0;   // exclusive block offsets
    if (t == 127) g_total = s[127];
}

__global__ void scanC_kernel(int n) {
    int i = blockIdx.x * blockDim.x + threadIdx.x;
    if (i < n) g_rowptr[i] += g_partial[i >> 10];
    if (i == n) g_rowptr[n] = g_total;
}

__global__ void fill_kernel(const int* __restrict__ src, const int* __restrict__ dst, int E) {
    int e = blockIdx.x * blockDim.x + threadIdx.x;
    if (e < E) {
        int d = dst[e];
        int p = atomicAdd(&g_cursor[d], 1);
        g_col[g_rowptr[d] + p] = src[e];
    }
}

__global__ void prep_w_kernel(const float* __restrict__ Wn1, const float* __restrict__ bn1,
                              const float* __restrict__ Ws1, const float* __restrict__ bs1,
                              const float* __restrict__ Wn2, const float* __restrict__ bn2,
                              const float* __restrict__ Ws2, const float* __restrict__ bs2) {
    int idx = blockIdx.x * blockDim.x + threadIdx.x;
    if (idx < 256 * DD) {
        int k = idx / DD, o = idx % DD;
        g_wcat[0][idx] = (k < DD) ? Wn1[o * DD + k] : Ws1[o * DD + (k - DD)];
        g_wcat[1][idx] = (k < DD) ? Wn2[o * DD + k] : Ws2[o * DD + (k - DD)];
    }
    if (idx < DD) {
        g_bias[0][idx] = bn1[idx] + bs1[idx];
        g_bias[1][idx] = bn2[idx] + bs2[idx];
    }
}

// ---------------------------------------------------------------------------
// Gather-side mean aggregation: one warp per node, pre-normalized by 1/deg.
__global__ __launch_bounds__(256) void agg_kernel(const float* __restrict__ feat,
                                                  float* __restrict__ out, int n) {
    const int warp = (blockIdx.x * blockDim.x + threadIdx.x) >> 5;
    if (warp >= n) return;
    const int lane = threadIdx.x & 31;
    const int c = lane << 2;
    const int beg = g_rowptr[warp];
    const int end = g_rowptr[warp + 1];

    float ax = 0.f, ay = 0.f, az = 0.f, aw = 0.f;
    for (int base = beg; base < end; base += 32) {
        const int idx = base + lane;
        const int sv = (idx < end) ? g_col[idx] : 0;
        const int cnt = min(end - base, 32);
#pragma unroll 4
        for (int j = 0; j < cnt; j++) {
            const int s = __shfl_sync(0xffffffffu, sv, j);
            const float4 v = *(const float4*)(feat + (size_t)s * DD + c);
            ax += v.x; ay += v.y; az += v.z; aw += v.w;
        }
    }
    const float inv = 1.0f / fmaxf((float)(end - beg), 1.0f);
    float4 r;
    r.x = ax * inv; r.y = ay * inv; r.z = az * inv; r.w = aw * inv;
    *(float4*)(out + (size_t)warp * DD + c) = r;
}

// ---------------------------------------------------------------------------
// Fused SGEMM with packed fp32x2 FMA (FFMA2).
// out[r][o] = relu?( [agg|A2][r][:] @ Wcat[:,o] + bias[o] ),  K=256
// Tile: BM=128, BN=128, BK=8; 256 threads; per-thread 8 rows x 4 float2 cols.
template <bool RELU>
__global__ __launch_bounds__(256) void gemm_kernel(const float* __restrict__ A2,
                                                   const float* __restrict__ Wcat,
                                                   const float* __restrict__ bias,
                                                   float* __restrict__ out, int n) {
    __shared__ float As[8][128];
    __shared__ float Bs[8][128];

    const int tid = threadIdx.x;
    const int block_row = blockIdx.x * 128;

    const int a_row = tid >> 1;            // 0..127
    const int a_k   = (tid & 1) << 2;      // 0 or 4
    const int g_row = block_row + a_row;
    const bool row_ok = g_row < n;
    const float* a1p = g_agg + (size_t)g_row * DD;
    const float* a2p = A2 + (size_t)g_row * DD;

    const int b_k   = tid >> 5;            // 0..7
    const int b_col = (tid & 31) << 2;     // 0..124

    const int tr = (tid >> 4) << 3;
    const int tc = (tid & 15) << 3;

    unsigned long long acc[8][4];          // 4x f32x2 per row (8 cols)
#pragma unroll
    for (int i = 0; i < 8; i++)
#pragma unroll
        for (int j = 0; j < 4; j++) acc[i][j] = 0ull;

    for (int k0 = 0; k0 < 256; k0 += 8) {
        float4 av = make_float4(0.f, 0.f, 0.f, 0.f);
        const int kk = k0 + a_k;
        if (row_ok) {
            av = (kk < 128) ? *(const float4*)(a1p + kk)
                            : *(const float4*)(a2p + (kk - 128));
        }
        const float4 bv = *(const float4*)(Wcat + (size_t)(k0 + b_k) * 128 + b_col);

        if (k0) __syncthreads();
        As[a_k + 0][a_row] = av.x;
        As[a_k + 1][a_row] = av.y;
        As[a_k + 2][a_row] = av.z;
        As[a_k + 3][a_row] = av.w;
        *(float4*)&Bs[b_k][b_col] = bv;
        __syncthreads();

#pragma unroll
        for (int p = 0; p < 8; p++) {
            float ar[8];
            unsigned long long br[4];
#pragma unroll
            for (int i = 0; i < 8; i++) ar[i] = As[p][tr + i];
            const unsigned long long* bp =
                (const unsigned long long*)&Bs[p][tc];
#pragma unroll
            for (int j = 0; j < 4; j++) br[j] = bp[j];
#pragma unroll
            for (int i = 0; i < 8; i++) {
                unsigned long long a2;
                asm("mov.b64 %0, {%1, %1};" : "=l"(a2) : "f"(ar[i]));
#pragma unroll
                for (int j = 0; j < 4; j++) {
                    asm("fma.rn.f32x2 %0, %1, %2, %0;"
                        : "+l"(acc[i][j]) : "l"(a2), "l"(br[j]));
                }
            }
        }
    }

    float bb[8];
#pragma unroll
    for (int j = 0; j < 8; j++) bb[j] = bias[tc + j];

#pragma unroll
    for (int i = 0; i < 8; i++) {
        int r = block_row + tr + i;
        if (r < n) {
            float v[8];
#pragma unroll
            for (int j = 0; j < 4; j++) {
                float lo, hi;
                asm("mov.b64 {%0, %1}, %2;" : "=f"(lo), "=f"(hi) : "l"(acc[i][j]));
                v[2 * j]     = lo + bb[2 * j];
                v[2 * j + 1] = hi + bb[2 * j + 1];
                if (RELU) {
                    v[2 * j]     = fmaxf(v[2 * j], 0.f);
                    v[2 * j + 1] = fmaxf(v[2 * j + 1], 0.f);
                }
            }
            float* op = out + (size_t)r * DD + tc;
            *(float4*)(op)     = make_float4(v[0], v[1], v[2], v[3]);
            *(float4*)(op + 4) = make_float4(v[4], v[5], v[6], v[7]);
        }
    }
}

// ---------------------------------------------------------------------------
extern "C" void kernel_launch(void* const* d_in, const int* in_sizes, int n_in,
                              void* d_out, int out_size) {
    const float* x   = (const float*)d_in[0];
    const int* ei    = (const int*)d_in[1];
    const float* Wn1 = (const float*)d_in[2];
    const float* bn1 = (const float*)d_in[3];
    const float* Ws1 = (const float*)d_in[4];
    const float* bs1 = (const float*)d_in[5];
    const float* Wn2 = (const float*)d_in[6];
    const float* bn2 = (const float*)d_in[7];
    const float* Ws2 = (const float*)d_in[8];
    const float* bs2 = (const float*)d_in[9];
    float* out = (float*)d_out;

    const int n = in_sizes[0] / DD;
    const int E = in_sizes[1] / 2;
    const int* src = ei;
    const int* dst = ei + E;

    float* d_h1;    cudaGetSymbolAddress((void**)&d_h1, g_h1);
    float* d_agg;   cudaGetSymbolAddress((void**)&d_agg, g_agg);
    int* d_deg;     cudaGetSymbolAddress((void**)&d_deg, g_deg);
    int* d_cursor;  cudaGetSymbolAddress((void**)&d_cursor, g_cursor);
    float* d_wcat0; cudaGetSymbolAddress((void**)&d_wcat0, g_wcat);
    float* d_bias0; cudaGetSymbolAddress((void**)&d_bias0, g_bias);

    const int threads = 256;
    const int nb = (n + 1023) / 1024;

    // --- CSR build ---
    zero_int2_kernel<<<(n + threads - 1) / threads, threads>>>(d_deg, d_cursor, n);
    prep_w_kernel<<<(256 * DD + threads - 1) / threads, threads>>>(Wn1, bn1, Ws1, bs1,
                                                                   Wn2, bn2, Ws2, bs2);
    deg_kernel<<<(E + threads - 1) / threads, threads>>>(dst, E);
    scanA_kernel<<<nb, 1024>>>(n);
    scanB_kernel<<<1, 128>>>(nb);
    scanC_kernel<<<(n + 1 + threads - 1) / threads, threads>>>(n);
    fill_kernel<<<(E + threads - 1) / threads, threads>>>(src, dst, E);

    const unsigned agg_threads_total = (unsigned)n * 32u;
    const unsigned agg_blocks = (agg_threads_total + threads - 1) / threads;

    // layer 1: mean-aggregate x -> agg, fused GEMM + relu -> h1
    agg_kernel<<<agg_blocks, threads>>>(x, d_agg, n);
    gemm_kernel<true><<<(n + 127) / 128, 256>>>(x, d_wcat0, d_bias0, d_h1, n);

    // layer 2: mean-aggregate h1 -> agg, fused GEMM -> out
    agg_kernel<<<agg_blocks, threads>>>(d_h1, d_agg, n);
    gemm_kernel<false><<<(n + 127) / 128, 256>>>(d_h1, d_wcat0 + 256 * DD, d_bias0 + DD,
                                                 out, n);
}